// round 1
// baseline (speedup 1.0000x reference)
#include <cuda_runtime.h>
#include <cstdint>
#include <cstddef>

// Problem constants
#define BATCH   32
#define DMODEL  2560
#define DINNER  5120
#define NSTATE  16
#define DTRANK  160
#define XDBDIM  192          // DTRANK + 2*NSTATE

// Split-K configs
#define SPLIT_IN   4         // K=2560 -> 640 each
#define SPLIT_XP   40        // K=5120 -> 128 each
#define SPLIT_OUT  8         // K=5120 -> 640 each

// -------- scratch (static device globals; no allocation) ----------
__device__ __align__(256) float g_xT[DMODEL * BATCH];
__device__ __align__(256) float g_part_in[(2 * SPLIT_IN) * BATCH * DINNER];
__device__ __align__(256) float g_convT[DINNER * BATCH];
__device__ __align__(256) float g_gT[DINNER * BATCH];
__device__ __align__(256) float g_part_b[SPLIT_XP * BATCH * XDBDIM];
__device__ __align__(256) float g_xdbT[XDBDIM * BATCH];
__device__ __align__(256) float g_zT[DINNER * BATCH];
__device__ __align__(256) float g_part_c[SPLIT_OUT * BATCH * DMODEL];

// -------- f32x2 helpers (Blackwell packed fp32; PTX-only pattern) ----------
__device__ __forceinline__ unsigned long long fma2(unsigned long long a,
                                                   unsigned long long x,
                                                   unsigned long long c) {
    unsigned long long r;
    asm("fma.rn.f32x2 %0, %1, %2, %3;" : "=l"(r) : "l"(a), "l"(x), "l"(c));
    return r;
}
__device__ __forceinline__ unsigned long long pack2(float v) {
    unsigned long long r;
    asm("mov.b64 %0, {%1, %1};" : "=l"(r) : "f"(v));
    return r;
}
__device__ __forceinline__ float2 unpk(unsigned long long v) {
    float2 r;
    asm("mov.b64 {%0, %1}, %2;" : "=f"(r.x), "=f"(r.y) : "l"(v));
    return r;
}
__device__ __forceinline__ float silu_f(float v) {
    return v / (1.f + __expf(-v));
}

// ===================================================================
// Transpose x (B, DMODEL) -> xT (DMODEL, B)
// ===================================================================
__global__ void __launch_bounds__(256) transpose_x_kernel(const float* __restrict__ x) {
    int k = blockIdx.x * 256 + threadIdx.x;   // 0..2559
    if (k >= DMODEL) return;
#pragma unroll
    for (int b = 0; b < BATCH; b++)
        g_xT[k * BATCH + b] = x[(size_t)b * DMODEL + k];
}

// ===================================================================
// Generic split-K GEMM tile: 128 threads, 128 rows x 32 batch.
// xT is (K, 32) row-major.  Writes partial to partZ[(b)*M + d].
// klen must be a multiple of 64.
// ===================================================================
__device__ __forceinline__ void gemm_tile(const float* __restrict__ W,
                                          const float* __restrict__ xT,
                                          float* __restrict__ partZ,
                                          int M, int K, int k0, int klen, int row0) {
    __shared__ float x_s[64 * 32];
    const int tid = threadIdx.x;
    const int rg = tid >> 2;   // 0..31 : row group (4 rows)
    const int bg = tid & 3;    // 0..3  : batch group (8 batches)
    const int d0 = row0 + rg * 4;
    int dcl = d0;
    if (dcl > M - 4) dcl = M - 4;   // clamp for safe loads (store guarded)

    const float4* w4[4];
#pragma unroll
    for (int i = 0; i < 4; i++)
        w4[i] = (const float4*)(W + (size_t)(dcl + i) * K + k0);

    unsigned long long acc[4][4];
#pragma unroll
    for (int i = 0; i < 4; i++)
#pragma unroll
        for (int p = 0; p < 4; p++) acc[i][p] = 0ull;

    for (int t = 0; t < klen; t += 64) {
        __syncthreads();
        {
            const float4* src = (const float4*)(xT + (size_t)(k0 + t) * BATCH);
            float4* dst = (float4*)x_s;
#pragma unroll
            for (int u = 0; u < 4; u++)
                dst[tid + u * 128] = src[tid + u * 128];
        }
        __syncthreads();

#pragma unroll 4
        for (int kk4 = 0; kk4 < 16; kk4++) {
            float4 w[4];
#pragma unroll
            for (int i = 0; i < 4; i++)
                w[i] = w4[i][(t >> 2) + kk4];
#pragma unroll
            for (int kk = 0; kk < 4; kk++) {
                const ulonglong2* xp =
                    (const ulonglong2*)&x_s[((kk4 << 2) + kk) * BATCH + bg * 8];
                ulonglong2 xa = xp[0];
                ulonglong2 xb = xp[1];
#pragma unroll
                for (int i = 0; i < 4; i++) {
                    float wa[4] = {w[i].x, w[i].y, w[i].z, w[i].w};
                    unsigned long long wp = pack2(wa[kk]);
                    acc[i][0] = fma2(wp, xa.x, acc[i][0]);
                    acc[i][1] = fma2(wp, xa.y, acc[i][1]);
                    acc[i][2] = fma2(wp, xb.x, acc[i][2]);
                    acc[i][3] = fma2(wp, xb.y, acc[i][3]);
                }
            }
        }
    }

    if (d0 < M) {
#pragma unroll
        for (int p = 0; p < 4; p++) {
            float2 f0 = unpk(acc[0][p]);
            float2 f1 = unpk(acc[1][p]);
            float2 f2 = unpk(acc[2][p]);
            float2 f3 = unpk(acc[3][p]);
            int b = bg * 8 + p * 2;
            float4 v0 = make_float4(f0.x, f1.x, f2.x, f3.x);
            float4 v1 = make_float4(f0.y, f1.y, f2.y, f3.y);
            *(float4*)&partZ[(size_t)b * M + d0] = v0;
            *(float4*)&partZ[(size_t)(b + 1) * M + d0] = v1;
        }
    }
}

// ---- wrappers ----
__global__ void __launch_bounds__(128)
gemm_in_kernel(const float* __restrict__ Wssm, const float* __restrict__ Wmlp) {
    int sel = blockIdx.y;          // 0: ssm, 1: mlp
    int z = blockIdx.z;            // 0..3
    const float* W = sel ? Wmlp : Wssm;
    float* partZ = g_part_in + (size_t)(sel * SPLIT_IN + z) * BATCH * DINNER;
    gemm_tile(W, g_xT, partZ, DINNER, DMODEL, z * 640, 640, blockIdx.x * 128);
}

__global__ void __launch_bounds__(128)
gemm_xp_kernel(const float* __restrict__ Wxp) {
    int z = blockIdx.z;            // 0..39
    float* partZ = g_part_b + (size_t)z * BATCH * XDBDIM;
    gemm_tile(Wxp, g_convT, partZ, XDBDIM, DINNER, z * 128, 128, blockIdx.x * 128);
}

__global__ void __launch_bounds__(128)
gemm_out_kernel(const float* __restrict__ Wout) {
    int z = blockIdx.z;            // 0..7
    float* partZ = g_part_c + (size_t)z * BATCH * DMODEL;
    gemm_tile(Wout, g_zT, partZ, DMODEL, DINNER, z * 640, 640, blockIdx.x * 128);
}

// ===================================================================
// Epilogue A: sum in_proj partials, depthwise conv + SiLU -> convT,
//             gate SiLU(res) -> gT
// ===================================================================
__global__ void __launch_bounds__(128)
epi_a_kernel(const float* __restrict__ conv_states,
             const float* __restrict__ conv_w,
             const float* __restrict__ conv_b) {
    int d = blockIdx.x * 128 + threadIdx.x;
    float xs[BATCH], res[BATCH];
#pragma unroll
    for (int b = 0; b < BATCH; b++) { xs[b] = 0.f; res[b] = 0.f; }
#pragma unroll
    for (int z = 0; z < SPLIT_IN; z++)
#pragma unroll
        for (int b = 0; b < BATCH; b++)
            xs[b] += g_part_in[(size_t)(z * BATCH + b) * DINNER + d];
#pragma unroll
    for (int z = SPLIT_IN; z < 2 * SPLIT_IN; z++)
#pragma unroll
        for (int b = 0; b < BATCH; b++)
            res[b] += g_part_in[(size_t)(z * BATCH + b) * DINNER + d];

    float cw0 = conv_w[d];
    float cw1 = conv_w[DINNER + d];
    float cw2 = conv_w[2 * DINNER + d];
    float cw3 = conv_w[3 * DINNER + d];
    float cb = conv_b[d];

#pragma unroll
    for (int b4 = 0; b4 < 8; b4++) {
        float cc[4], gw[4];
#pragma unroll
        for (int h = 0; h < 4; h++) {
            int b = b4 * 4 + h;
            float conv = conv_states[(size_t)(1 * BATCH + b) * DINNER + d] * cw0
                       + conv_states[(size_t)(2 * BATCH + b) * DINNER + d] * cw1
                       + conv_states[(size_t)(3 * BATCH + b) * DINNER + d] * cw2
                       + xs[b] * cw3 + cb;
            cc[h] = silu_f(conv);
            gw[h] = silu_f(res[b]);
        }
        *(float4*)&g_convT[(size_t)d * BATCH + b4 * 4] =
            make_float4(cc[0], cc[1], cc[2], cc[3]);
        *(float4*)&g_gT[(size_t)d * BATCH + b4 * 4] =
            make_float4(gw[0], gw[1], gw[2], gw[3]);
    }
}

// ===================================================================
// Epilogue B: sum x_proj partials -> x_dbT (192, 32)
// ===================================================================
__global__ void __launch_bounds__(256) epi_b_kernel() {
    int t = blockIdx.x * 256 + threadIdx.x;   // 0..6143
    int b = t / XDBDIM;
    int r = t - b * XDBDIM;
    float s = 0.f;
#pragma unroll 8
    for (int z = 0; z < SPLIT_XP; z++)
        s += g_part_b[(size_t)(z * BATCH + b) * XDBDIM + r];
    g_xdbT[(size_t)r * BATCH + b] = s;
}

// ===================================================================
// SSM kernel: dt GEMV + softplus + state scan + gate -> zT
// grid (DINNER/128, 4), block 128; blockIdx.y selects 8-batch group
// ===================================================================
__global__ void __launch_bounds__(128)
ssm_kernel(const float* __restrict__ W_dt, const float* __restrict__ dt_bias,
           const float* __restrict__ A_log, const float* __restrict__ Dv,
           const float* __restrict__ ssm_state) {
    __shared__ float xdb_s[XDBDIM * 8];
    const int by = blockIdx.y;
    for (int u = threadIdx.x; u < XDBDIM * 8; u += 128) {
        int r = u >> 3, bb = u & 7;
        xdb_s[u] = g_xdbT[(size_t)r * BATCH + by * 8 + bb];
    }
    __syncthreads();

    const int d = blockIdx.x * 128 + threadIdx.x;

    float accdt[8];
#pragma unroll
    for (int bb = 0; bb < 8; bb++) accdt[bb] = 0.f;

    const float4* wd = (const float4*)(W_dt + (size_t)d * DTRANK);
#pragma unroll 10
    for (int r4 = 0; r4 < DTRANK / 4; r4++) {
        float4 w = wd[r4];
        float wa[4] = {w.x, w.y, w.z, w.w};
#pragma unroll
        for (int j = 0; j < 4; j++)
#pragma unroll
            for (int bb = 0; bb < 8; bb++)
                accdt[bb] += wa[j] * xdb_s[((r4 * 4 + j) << 3) + bb];
    }

    float a[NSTATE];
    const float4* al = (const float4*)(A_log + (size_t)d * NSTATE);
#pragma unroll
    for (int n4 = 0; n4 < 4; n4++) {
        float4 v = al[n4];
        a[n4 * 4 + 0] = -__expf(v.x);
        a[n4 * 4 + 1] = -__expf(v.y);
        a[n4 * 4 + 2] = -__expf(v.z);
        a[n4 * 4 + 3] = -__expf(v.w);
    }
    float Dd = Dv[d];
    float bias = dt_bias[d];

    float4 cv0 = *(const float4*)&g_convT[(size_t)d * BATCH + by * 8];
    float4 cv1 = *(const float4*)&g_convT[(size_t)d * BATCH + by * 8 + 4];
    float4 gv0 = *(const float4*)&g_gT[(size_t)d * BATCH + by * 8];
    float4 gv1 = *(const float4*)&g_gT[(size_t)d * BATCH + by * 8 + 4];
    float cv[8] = {cv0.x, cv0.y, cv0.z, cv0.w, cv1.x, cv1.y, cv1.z, cv1.w};
    float gv[8] = {gv0.x, gv0.y, gv0.z, gv0.w, gv1.x, gv1.y, gv1.z, gv1.w};
    float zv[8];

#pragma unroll
    for (int bb = 0; bb < 8; bb++) {
        int b = by * 8 + bb;
        float dtv = accdt[bb] + bias;
        float dt = dtv > 20.f ? dtv : log1pf(__expf(dtv));
        float c = cv[bb];
        float y = Dd * c;
        const float4* s4 =
            (const float4*)(ssm_state + ((size_t)b * DINNER + d) * NSTATE);
#pragma unroll
        for (int n4 = 0; n4 < 4; n4++) {
            float4 s = s4[n4];
            float sa[4] = {s.x, s.y, s.z, s.w};
#pragma unroll
            for (int h = 0; h < 4; h++) {
                int n = n4 * 4 + h;
                float dA = __expf(dt * a[n]);
                float hv = sa[h] * dA + dt * xdb_s[((DTRANK + n) << 3) + bb] * c;
                y += hv * xdb_s[((DTRANK + NSTATE + n) << 3) + bb];
            }
        }
        zv[bb] = y * gv[bb];
    }
    *(float4*)&g_zT[(size_t)d * BATCH + by * 8] =
        make_float4(zv[0], zv[1], zv[2], zv[3]);
    *(float4*)&g_zT[(size_t)d * BATCH + by * 8 + 4] =
        make_float4(zv[4], zv[5], zv[6], zv[7]);
}

// ===================================================================
// Epilogue C: sum out_proj partials -> out (B, DMODEL)
// ===================================================================
__global__ void __launch_bounds__(256) epi_c_kernel(float* __restrict__ out) {
    int t = blockIdx.x * 256 + threadIdx.x;   // 0..81919 == b*2560+m
    float s = 0.f;
#pragma unroll
    for (int z = 0; z < SPLIT_OUT; z++)
        s += g_part_c[(size_t)z * BATCH * DMODEL + t];
    out[t] = s;
}

// ===================================================================
extern "C" void kernel_launch(void* const* d_in, const int* in_sizes, int n_in,
                              void* d_out, int out_size) {
    const float* x    = (const float*)d_in[0];
    const float* cs   = (const float*)d_in[1];
    const float* cw   = (const float*)d_in[2];
    const float* cb   = (const float*)d_in[3];
    const float* Wssm = (const float*)d_in[4];
    const float* Wmlp = (const float*)d_in[5];
    const float* Wout = (const float*)d_in[6];
    const float* Wxp  = (const float*)d_in[7];
    const float* Wdt  = (const float*)d_in[8];
    const float* dtb  = (const float*)d_in[9];
    const float* Alog = (const float*)d_in[10];
    const float* Dv   = (const float*)d_in[11];
    const float* sst  = (const float*)d_in[12];
    float* out = (float*)d_out;

    transpose_x_kernel<<<10, 256>>>(x);
    gemm_in_kernel<<<dim3(DINNER / 128, 2, SPLIT_IN), 128>>>(Wssm, Wmlp);
    epi_a_kernel<<<DINNER / 128, 128>>>(cs, cw, cb);
    gemm_xp_kernel<<<dim3(2, 1, SPLIT_XP), 128>>>(Wxp);
    epi_b_kernel<<<(XDBDIM * BATCH) / 256, 256>>>();
    ssm_kernel<<<dim3(DINNER / 128, 4), 128>>>(Wdt, dtb, Alog, Dv, sst);
    gemm_out_kernel<<<dim3(DMODEL / 128, 1, SPLIT_OUT), 128>>>(Wout);
    epi_c_kernel<<<(BATCH * DMODEL) / 256, 256>>>(out);
}

// round 2
// speedup vs baseline: 1.0794x; 1.0794x over previous
#include <cuda_runtime.h>
#include <cstdint>
#include <cstddef>

// Problem constants
#define BATCH   32
#define DMODEL  2560
#define DINNER  5120
#define NSTATE  16
#define DTRANK  160
#define XDBDIM  192          // DTRANK + 2*NSTATE

// Split-K configs
#define SPLIT_IN   5         // K=2560 -> 512 each
#define SPLIT_XP   80        // K=5120 -> 64 each
#define SPLIT_OUT  20        // K=5120 -> 256 each

#define TILE_K 64

// -------- scratch (static device globals; no allocation) ----------
__device__ __align__(256) float g_xT[DMODEL * BATCH];
__device__ __align__(256) float g_part_in[(2 * SPLIT_IN) * BATCH * DINNER];
__device__ __align__(256) float g_convT[DINNER * BATCH];
__device__ __align__(256) float g_gT[DINNER * BATCH];
__device__ __align__(256) float g_part_b[SPLIT_XP * BATCH * XDBDIM];
__device__ __align__(256) float g_xdbT[XDBDIM * BATCH];
__device__ __align__(256) float g_zT[DINNER * BATCH];
__device__ __align__(256) float g_part_c[SPLIT_OUT * BATCH * DMODEL];

// -------- f32x2 helpers (Blackwell packed fp32; PTX-only pattern) ----------
__device__ __forceinline__ unsigned long long fma2(unsigned long long a,
                                                   unsigned long long x,
                                                   unsigned long long c) {
    unsigned long long r;
    asm("fma.rn.f32x2 %0, %1, %2, %3;" : "=l"(r) : "l"(a), "l"(x), "l"(c));
    return r;
}
__device__ __forceinline__ unsigned long long pack2(float v) {
    unsigned long long r;
    asm("mov.b64 %0, {%1, %1};" : "=l"(r) : "f"(v));
    return r;
}
__device__ __forceinline__ float2 unpk(unsigned long long v) {
    float2 r;
    asm("mov.b64 {%0, %1}, %2;" : "=f"(r.x), "=f"(r.y) : "l"(v));
    return r;
}
__device__ __forceinline__ float silu_f(float v) {
    return v / (1.f + __expf(-v));
}

// -------- cp.async helpers ----------
__device__ __forceinline__ uint32_t smem_u32(const void* p) {
    uint32_t r;
    asm("{.reg .u64 t; cvta.to.shared.u64 t, %1; cvt.u32.u64 %0, t;}"
        : "=r"(r) : "l"(p));
    return r;
}
__device__ __forceinline__ void cp_async16(uint32_t dst, const void* src) {
    asm volatile("cp.async.ca.shared.global [%0], [%1], 16;\n" ::"r"(dst), "l"(src));
}
__device__ __forceinline__ void cp_commit() {
    asm volatile("cp.async.commit_group;\n");
}
template <int N>
__device__ __forceinline__ void cp_wait() {
    asm volatile("cp.async.wait_group %0;\n" ::"n"(N));
}

// ===================================================================
// Transpose x (B, DMODEL) -> xT (DMODEL, B) via smem tiles
// grid 80 blocks, block (32,8)
// ===================================================================
__global__ void __launch_bounds__(256) transpose_x_kernel(const float* __restrict__ x) {
    __shared__ float t[32][33];
    int k0 = blockIdx.x * 32;
    int tx = threadIdx.x, ty = threadIdx.y;
#pragma unroll
    for (int i = 0; i < 4; i++) {
        int b = ty + 8 * i;
        t[b][tx] = x[(size_t)b * DMODEL + k0 + tx];
    }
    __syncthreads();
#pragma unroll
    for (int i = 0; i < 4; i++) {
        int kk = ty + 8 * i;
        g_xT[(size_t)(k0 + kk) * BATCH + tx] = t[tx][kk];
    }
}

// ===================================================================
// Pipelined split-K GEMM tile: 256 threads, 128 rows x 32 batch.
// thread = 2 rows x 8 batches. Weight prefetch ring depth 4 (regs),
// x tiles double-buffered in smem via cp.async.
// xT is (K, 32) row-major. Writes partial to partZ[b*M + d].
// klen must be a multiple of 64.
// ===================================================================
__device__ __forceinline__ void gemm_tile2(const float* __restrict__ W,
                                           const float* __restrict__ xT,
                                           float* __restrict__ partZ,
                                           int M, int K, int k0, int klen, int row0) {
    __shared__ __align__(16) float x_s[2][TILE_K * 32];
    const int tid = threadIdx.x;
    const int rg = tid >> 2;   // 0..63 : 2-row group
    const int bg = tid & 3;    // 0..3  : 8-batch group
    const int d0 = row0 + rg * 2;
    int dcl = d0 > M - 2 ? M - 2 : d0;   // clamp for safe loads (store guarded)

    const float4* w0 = (const float4*)(W + (size_t)dcl * K + k0);
    const float4* w1 = (const float4*)(W + (size_t)(dcl + 1) * K + k0);

    const int ntiles = klen / TILE_K;
    const int nkk4 = klen / 4;

    const uint32_t s0 = smem_u32(&x_s[0][0]);
    const uint32_t s1 = smem_u32(&x_s[1][0]);

    // fill tile 0
    {
        const float* src = xT + (size_t)k0 * BATCH;
        cp_async16(s0 + tid * 16, src + tid * 4);
        cp_async16(s0 + tid * 16 + 4096, src + tid * 4 + 1024);
        cp_commit();
    }

    // weight prefetch ring, depth 4 (kk4 granularity)
    float4 wb0[4], wb1[4];
#pragma unroll
    for (int i = 0; i < 4; i++) {
        wb0[i] = w0[i];
        wb1[i] = w1[i];
    }

    unsigned long long acc[2][4];
#pragma unroll
    for (int r = 0; r < 2; r++)
#pragma unroll
        for (int p = 0; p < 4; p++) acc[r][p] = 0ull;

    for (int t = 0; t < ntiles; t++) {
        if (t + 1 < ntiles) {
            const float* src = xT + (size_t)(k0 + (t + 1) * TILE_K) * BATCH;
            uint32_t dst = ((t + 1) & 1) ? s1 : s0;
            cp_async16(dst + tid * 16, src + tid * 4);
            cp_async16(dst + tid * 16 + 4096, src + tid * 4 + 1024);
            cp_commit();
            cp_wait<1>();
        } else {
            cp_wait<0>();
        }
        __syncthreads();
        const float* xs = x_s[t & 1];
        const int jbase = t * 16;
#pragma unroll
        for (int jj = 0; jj < 16; jj++) {
            float4 wA = wb0[jj & 3];
            float4 wB = wb1[jj & 3];
            float wAa[4] = {wA.x, wA.y, wA.z, wA.w};
            float wBa[4] = {wB.x, wB.y, wB.z, wB.w};
#pragma unroll
            for (int kk = 0; kk < 4; kk++) {
                const ulonglong2* xp =
                    (const ulonglong2*)&xs[(jj * 4 + kk) * BATCH + bg * 8];
                ulonglong2 xa = xp[0];
                ulonglong2 xb = xp[1];
                unsigned long long wpA = pack2(wAa[kk]);
                unsigned long long wpB = pack2(wBa[kk]);
                acc[0][0] = fma2(wpA, xa.x, acc[0][0]);
                acc[0][1] = fma2(wpA, xa.y, acc[0][1]);
                acc[0][2] = fma2(wpA, xb.x, acc[0][2]);
                acc[0][3] = fma2(wpA, xb.y, acc[0][3]);
                acc[1][0] = fma2(wpB, xa.x, acc[1][0]);
                acc[1][1] = fma2(wpB, xa.y, acc[1][1]);
                acc[1][2] = fma2(wpB, xb.x, acc[1][2]);
                acc[1][3] = fma2(wpB, xb.y, acc[1][3]);
            }
            int jn = jbase + jj + 4;
            if (jn < nkk4) {
                wb0[jj & 3] = w0[jn];
                wb1[jj & 3] = w1[jn];
            }
        }
        __syncthreads();
    }

    if (d0 <= M - 2) {
#pragma unroll
        for (int p = 0; p < 4; p++) {
            float2 a0 = unpk(acc[0][p]);   // row d0,   batches b, b+1
            float2 a1 = unpk(acc[1][p]);   // row d0+1, batches b, b+1
            int b = bg * 8 + 2 * p;
            *(float2*)&partZ[(size_t)b * M + d0] = make_float2(a0.x, a1.x);
            *(float2*)&partZ[(size_t)(b + 1) * M + d0] = make_float2(a0.y, a1.y);
        }
    }
}

// ---- wrappers ----
__global__ void __launch_bounds__(256, 3)
gemm_in_kernel(const float* __restrict__ Wssm, const float* __restrict__ Wmlp) {
    int sel = blockIdx.y;          // 0: ssm, 1: mlp
    int z = blockIdx.z;            // 0..SPLIT_IN-1
    const float* W = sel ? Wmlp : Wssm;
    float* partZ = g_part_in + (size_t)(sel * SPLIT_IN + z) * BATCH * DINNER;
    gemm_tile2(W, g_xT, partZ, DINNER, DMODEL, z * (DMODEL / SPLIT_IN),
               DMODEL / SPLIT_IN, blockIdx.x * 128);
}

__global__ void __launch_bounds__(256, 3)
gemm_xp_kernel(const float* __restrict__ Wxp) {
    int z = blockIdx.z;            // 0..SPLIT_XP-1
    float* partZ = g_part_b + (size_t)z * BATCH * XDBDIM;
    gemm_tile2(Wxp, g_convT, partZ, XDBDIM, DINNER, z * (DINNER / SPLIT_XP),
               DINNER / SPLIT_XP, blockIdx.x * 128);
}

__global__ void __launch_bounds__(256, 3)
gemm_out_kernel(const float* __restrict__ Wout) {
    int z = blockIdx.z;            // 0..SPLIT_OUT-1
    float* partZ = g_part_c + (size_t)z * BATCH * DMODEL;
    gemm_tile2(Wout, g_zT, partZ, DMODEL, DINNER, z * (DINNER / SPLIT_OUT),
               DINNER / SPLIT_OUT, blockIdx.x * 128);
}

// ===================================================================
// Epilogue A: sum in_proj partials, depthwise conv + SiLU -> convT,
//             gate SiLU(res) -> gT
// ===================================================================
__global__ void __launch_bounds__(128)
epi_a_kernel(const float* __restrict__ conv_states,
             const float* __restrict__ conv_w,
             const float* __restrict__ conv_b) {
    int d = blockIdx.x * 128 + threadIdx.x;
    float xs[BATCH], res[BATCH];
#pragma unroll
    for (int b = 0; b < BATCH; b++) { xs[b] = 0.f; res[b] = 0.f; }
#pragma unroll
    for (int z = 0; z < SPLIT_IN; z++)
#pragma unroll
        for (int b = 0; b < BATCH; b++)
            xs[b] += g_part_in[(size_t)(z * BATCH + b) * DINNER + d];
#pragma unroll
    for (int z = SPLIT_IN; z < 2 * SPLIT_IN; z++)
#pragma unroll
        for (int b = 0; b < BATCH; b++)
            res[b] += g_part_in[(size_t)(z * BATCH + b) * DINNER + d];

    float cw0 = conv_w[d];
    float cw1 = conv_w[DINNER + d];
    float cw2 = conv_w[2 * DINNER + d];
    float cw3 = conv_w[3 * DINNER + d];
    float cb = conv_b[d];

#pragma unroll
    for (int b4 = 0; b4 < 8; b4++) {
        float cc[4], gw[4];
#pragma unroll
        for (int h = 0; h < 4; h++) {
            int b = b4 * 4 + h;
            float conv = conv_states[(size_t)(1 * BATCH + b) * DINNER + d] * cw0
                       + conv_states[(size_t)(2 * BATCH + b) * DINNER + d] * cw1
                       + conv_states[(size_t)(3 * BATCH + b) * DINNER + d] * cw2
                       + xs[b] * cw3 + cb;
            cc[h] = silu_f(conv);
            gw[h] = silu_f(res[b]);
        }
        *(float4*)&g_convT[(size_t)d * BATCH + b4 * 4] =
            make_float4(cc[0], cc[1], cc[2], cc[3]);
        *(float4*)&g_gT[(size_t)d * BATCH + b4 * 4] =
            make_float4(gw[0], gw[1], gw[2], gw[3]);
    }
}

// ===================================================================
// Epilogue B: sum x_proj partials -> x_dbT (192, 32)
// ===================================================================
__global__ void __launch_bounds__(256) epi_b_kernel() {
    int t = blockIdx.x * 256 + threadIdx.x;   // 0..6143
    int b = t / XDBDIM;
    int r = t - b * XDBDIM;
    float s = 0.f;
#pragma unroll 8
    for (int z = 0; z < SPLIT_XP; z++)
        s += g_part_b[(size_t)(z * BATCH + b) * XDBDIM + r];
    g_xdbT[(size_t)r * BATCH + b] = s;
}

// ===================================================================
// SSM kernel: dt GEMV + softplus + state scan + gate -> zT
// grid (DINNER/128, 8), block 128; blockIdx.y selects 4-batch group
// ===================================================================
#define SSM_BB 4
__global__ void __launch_bounds__(128)
ssm_kernel(const float* __restrict__ W_dt, const float* __restrict__ dt_bias,
           const float* __restrict__ A_log, const float* __restrict__ Dv,
           const float* __restrict__ ssm_state) {
    __shared__ float xdb_s[XDBDIM * SSM_BB];
    const int by = blockIdx.y;
    for (int u = threadIdx.x; u < XDBDIM * SSM_BB; u += 128) {
        int r = u >> 2, bb = u & 3;
        xdb_s[u] = g_xdbT[(size_t)r * BATCH + by * SSM_BB + bb];
    }
    __syncthreads();

    const int d = blockIdx.x * 128 + threadIdx.x;

    float accdt[SSM_BB];
#pragma unroll
    for (int bb = 0; bb < SSM_BB; bb++) accdt[bb] = 0.f;

    const float4* wd = (const float4*)(W_dt + (size_t)d * DTRANK);
#pragma unroll 10
    for (int r4 = 0; r4 < DTRANK / 4; r4++) {
        float4 w = wd[r4];
        float wa[4] = {w.x, w.y, w.z, w.w};
#pragma unroll
        for (int j = 0; j < 4; j++) {
            float4 xv = *(const float4*)&xdb_s[(r4 * 4 + j) * SSM_BB];
            accdt[0] += wa[j] * xv.x;
            accdt[1] += wa[j] * xv.y;
            accdt[2] += wa[j] * xv.z;
            accdt[3] += wa[j] * xv.w;
        }
    }

    float a[NSTATE];
    const float4* al = (const float4*)(A_log + (size_t)d * NSTATE);
#pragma unroll
    for (int n4 = 0; n4 < 4; n4++) {
        float4 v = al[n4];
        a[n4 * 4 + 0] = -__expf(v.x);
        a[n4 * 4 + 1] = -__expf(v.y);
        a[n4 * 4 + 2] = -__expf(v.z);
        a[n4 * 4 + 3] = -__expf(v.w);
    }
    float Dd = Dv[d];
    float bias = dt_bias[d];

    float4 cv4 = *(const float4*)&g_convT[(size_t)d * BATCH + by * SSM_BB];
    float4 gv4 = *(const float4*)&g_gT[(size_t)d * BATCH + by * SSM_BB];
    float cv[SSM_BB] = {cv4.x, cv4.y, cv4.z, cv4.w};
    float gv[SSM_BB] = {gv4.x, gv4.y, gv4.z, gv4.w};
    float zv[SSM_BB];

#pragma unroll
    for (int bb = 0; bb < SSM_BB; bb++) {
        int b = by * SSM_BB + bb;
        float dtv = accdt[bb] + bias;
        float dt = dtv > 20.f ? dtv : log1pf(__expf(dtv));
        float c = cv[bb];
        float y = Dd * c;
        const float4* s4 =
            (const float4*)(ssm_state + ((size_t)b * DINNER + d) * NSTATE);
#pragma unroll
        for (int n4 = 0; n4 < 4; n4++) {
            float4 s = s4[n4];
            float sa[4] = {s.x, s.y, s.z, s.w};
#pragma unroll
            for (int h = 0; h < 4; h++) {
                int n = n4 * 4 + h;
                float dA = __expf(dt * a[n]);
                float hv = sa[h] * dA + dt * xdb_s[(DTRANK + n) * SSM_BB + bb] * c;
                y += hv * xdb_s[(DTRANK + NSTATE + n) * SSM_BB + bb];
            }
        }
        zv[bb] = y * gv[bb];
    }
    *(float4*)&g_zT[(size_t)d * BATCH + by * SSM_BB] =
        make_float4(zv[0], zv[1], zv[2], zv[3]);
}

// ===================================================================
// Epilogue C: sum out_proj partials -> out (B, DMODEL)
// ===================================================================
__global__ void __launch_bounds__(256) epi_c_kernel(float* __restrict__ out) {
    int t = blockIdx.x * 256 + threadIdx.x;   // b*2560+m
    float s = 0.f;
#pragma unroll
    for (int z = 0; z < SPLIT_OUT; z++)
        s += g_part_c[(size_t)z * BATCH * DMODEL + t];
    out[t] = s;
}

// ===================================================================
extern "C" void kernel_launch(void* const* d_in, const int* in_sizes, int n_in,
                              void* d_out, int out_size) {
    const float* x    = (const float*)d_in[0];
    const float* cs   = (const float*)d_in[1];
    const float* cw   = (const float*)d_in[2];
    const float* cb   = (const float*)d_in[3];
    const float* Wssm = (const float*)d_in[4];
    const float* Wmlp = (const float*)d_in[5];
    const float* Wout = (const float*)d_in[6];
    const float* Wxp  = (const float*)d_in[7];
    const float* Wdt  = (const float*)d_in[8];
    const float* dtb  = (const float*)d_in[9];
    const float* Alog = (const float*)d_in[10];
    const float* Dv   = (const float*)d_in[11];
    const float* sst  = (const float*)d_in[12];
    float* out = (float*)d_out;

    transpose_x_kernel<<<DMODEL / 32, dim3(32, 8)>>>(x);
    gemm_in_kernel<<<dim3(DINNER / 128, 2, SPLIT_IN), 256>>>(Wssm, Wmlp);
    epi_a_kernel<<<DINNER / 128, 128>>>(cs, cw, cb);
    gemm_xp_kernel<<<dim3(2, 1, SPLIT_XP), 256>>>(Wxp);
    epi_b_kernel<<<(XDBDIM * BATCH) / 256, 256>>>();
    ssm_kernel<<<dim3(DINNER / 128, 8), 128>>>(Wdt, dtb, Alog, Dv, sst);
    gemm_out_kernel<<<dim3(DMODEL / 128, 1, SPLIT_OUT), 256>>>(Wout);
    epi_c_kernel<<<(BATCH * DMODEL) / 256, 256>>>(out);
}